// round 13
// baseline (speedup 1.0000x reference)
#include <cuda_runtime.h>
#include <cuda_bf16.h>
#include <cstdint>
#include <math.h>

// ---------------- problem constants ----------------
#define NB   32
#define HH   32
#define WW   32
#define NPTS 32768
#define DIM  256
#define KC   1024
#define DECAY 0.99f
#define ONE_MINUS_DECAY 0.01f
#define EPS 1e-5f
#define BETA 0.25f
#define ZE_ELEMS (NB*DIM*HH*WW)

// output layout
#define OFF_ZQ    0
#define OFF_LOSS  8388608
#define OFF_IDX   8388609
#define OFF_EMB   8421377
#define OFF_CS    8683521
#define OFF_EMAW  8684545

// ---------------- GEMM config ----------------
// score = e2 - 2*(A1.B1 + A1.B2)  (A2.B1 dropped; guarded by MARGIN + exact refine)
#define K3A   256          // A row: just bf16(z)
#define K3B   512          // B row: [B1 | B2]
#define MT    128
#define NTT   128
#define NTILES 8
#define KTILE 32           // bf16 per smem tile chunk (64 bytes)
#define NKT   16           // K3B / KTILE
#define PITCH 80
#define ABUFB (MT * PITCH)
#define MARGIN 0.8f

// ---------------- device scratch ----------------
__device__ float g_flatz[NPTS * DIM];
__device__ float g_e2[KC];
__device__ int   g_idx[NPTS];
__device__ float g_counts[KC];
__device__ float g_dw[KC * DIM];
__device__ float g_loss;
__device__ __align__(16) __nv_bfloat16 g_A[(size_t)NPTS * K3A];  // 16 MB
__device__ __align__(16) __nv_bfloat16 g_B[(size_t)KC * K3B];    // 1 MB
__device__ int g_nflag;
__device__ int g_flaglist[NPTS];
__device__ unsigned long long g_bestf[NPTS];

__device__ __forceinline__ uint32_t smem_u32(const void* p) {
    uint32_t a;
    asm("{ .reg .u64 t; cvta.to.shared.u64 t, %1; cvt.u32.u64 %0, t; }" : "=r"(a) : "l"(p));
    return a;
}
__device__ __forceinline__ void ldsm_x4(uint32_t& r0, uint32_t& r1, uint32_t& r2, uint32_t& r3, uint32_t a) {
    asm volatile("ldmatrix.sync.aligned.m8n8.x4.shared.b16 {%0,%1,%2,%3}, [%4];"
                 : "=r"(r0), "=r"(r1), "=r"(r2), "=r"(r3) : "r"(a));
}
__device__ __forceinline__ void mma16816(float* c, uint32_t a0, uint32_t a1, uint32_t a2, uint32_t a3,
                                         uint32_t b0, uint32_t b1) {
    asm volatile("mma.sync.aligned.m16n8k16.row.col.f32.bf16.bf16.f32 "
                 "{%0,%1,%2,%3}, {%4,%5,%6,%7}, {%8,%9}, {%0,%1,%2,%3};"
                 : "+f"(c[0]), "+f"(c[1]), "+f"(c[2]), "+f"(c[3])
                 : "r"(a0), "r"(a1), "r"(a2), "r"(a3), "r"(b0), "r"(b1));
}
#define CP_ASYNC16(sm, gm) asm volatile("cp.async.cg.shared.global [%0], [%1], 16;" :: "r"(sm), "l"(gm))
#define CP_COMMIT()        asm volatile("cp.async.commit_group;" ::: "memory")
#define CP_WAIT0()         asm volatile("cp.async.wait_group 0;" ::: "memory")

__device__ __forceinline__ unsigned int fsort(float s) {
    unsigned int u = __float_as_uint(s);
    return (u & 0x80000000u) ? ~u : (u | 0x80000000u);
}

// ---------------- K0 (#1) ----------------
__global__ void k_init() {
    int i = blockIdx.x * blockDim.x + threadIdx.x;
    if (i < KC * DIM) g_dw[i] = 0.0f;
    if (i < KC)       g_counts[i] = 0.0f;
    if (i == 0)       { g_loss = 0.0f; g_nflag = 0; }
}

// ---------------- K1 (#2): transpose + bf16 of z ----------------
__global__ void k_split_z(const float* __restrict__ ze) {
    __shared__ float ts[128][17];
    int b  = blockIdx.x;
    int n0 = (b >> 1) * 16;
    int d0 = (b & 1) * 128;
    int bz = n0 >> 10;
    int hw0 = n0 & 1023;
    int t = threadIdx.x;

    const float* src = ze + (size_t)bz * DIM * (HH * WW) + (size_t)d0 * (HH * WW) + hw0;
    #pragma unroll
    for (int i = 0; i < 2; i++) {
        int chunk = t + i * 256;
        int d = chunk >> 2, c = chunk & 3;
        float4 v = *(const float4*)(src + (size_t)d * (HH * WW) + c * 4);
        ts[d][c * 4 + 0] = v.x;
        ts[d][c * 4 + 1] = v.y;
        ts[d][c * 4 + 2] = v.z;
        ts[d][c * 4 + 3] = v.w;
    }
    __syncthreads();

    int n_l = t >> 4, c16 = t & 15;
    int n = n0 + n_l;
    int dd0 = c16 * 8;
    float v[8];
    #pragma unroll
    for (int j = 0; j < 8; j++) v[j] = ts[dd0 + j][n_l];

    float4* fz = (float4*)&g_flatz[(size_t)n * DIM + d0 + dd0];
    fz[0] = make_float4(v[0], v[1], v[2], v[3]);
    fz[1] = make_float4(v[4], v[5], v[6], v[7]);

    uint4 p1;
    uint32_t* w1 = (uint32_t*)&p1;
    #pragma unroll
    for (int j2 = 0; j2 < 4; j2++) {
        __nv_bfloat162 hp(__float2bfloat16(v[2 * j2]), __float2bfloat16(v[2 * j2 + 1]));
        w1[j2] = *(uint32_t*)&hp;
    }
    *(uint4*)(&g_A[(size_t)n * K3A + d0 + dd0]) = p1;
}

// ---------------- K1b (#3): split emb [B1|B2] + ||e||^2 ----------------
__global__ void k_split_emb(const float* __restrict__ emb) {
    int k = blockIdx.x, t = threadIdx.x;
    float v = emb[k * DIM + t];
    __nv_bfloat16 b1 = __float2bfloat16(v);
    __nv_bfloat16 b2 = __float2bfloat16(v - __bfloat162float(b1));
    size_t base = (size_t)k * K3B + t;
    g_B[base]       = b1;
    g_B[base + 256] = b2;
    float s = v * v;
    #pragma unroll
    for (int o = 16; o > 0; o >>= 1) s += __shfl_down_sync(0xffffffffu, s, o);
    __shared__ float ws[8];
    if ((t & 31) == 0) ws[t >> 5] = s;
    __syncthreads();
    if (t == 0) {
        float tot = 0.f;
        #pragma unroll
        for (int w = 0; w < 8; w++) tot += ws[w];
        g_e2[k] = tot;
    }
}

// ---------------- K2 (#4, ncu slot): HMMA GEMM + fused argmin ----------------
// B cols walk 0..511 (kt), A chunk = kt&7 (A reused for both B halves).
__global__ __launch_bounds__(256, 2) void k_argmin_mma() {
    __shared__ __align__(128) char Abuf[2][ABUFB];
    __shared__ __align__(128) char Bbuf[2][ABUFB];
    __shared__ float e2s[NTT];
    __shared__ float sv1[2][MT], sv2[2][MT];
    __shared__ int   si[2][MT];

    int tid  = threadIdx.x;
    int lane = tid & 31;
    int w    = tid >> 5;
    int mgrp = w & 3, nhalf = w >> 2;
    int m0   = blockIdx.x * MT;
    int m0w  = mgrp * 32;

    int lr = tid >> 2, lc = tid & 3;
    const char* Ag0 = (const char*)g_A + ((size_t)(m0 + lr) * K3A) * 2 + lc * 16;
    uint32_t stA = lr * PITCH + lc * 16;

    uint32_t sA = smem_u32(Abuf);
    uint32_t sB = smem_u32(Bbuf);

    uint32_t aoff0 = (m0w + (lane & 15)) * PITCH + (lane >> 4) * 16;
    uint32_t boff0 = (nhalf * 64 + (lane & 7) + ((lane >> 4) << 3)) * PITCH + ((lane >> 3) & 1) * 16;

    float B1r[4] = {3.4e38f, 3.4e38f, 3.4e38f, 3.4e38f};
    float B2r[4] = {3.4e38f, 3.4e38f, 3.4e38f, 3.4e38f};
    int   I1r[4] = {0, 0, 0, 0};

    for (int nt = 0; nt < NTILES; nt++) {
        if (tid < NTT) e2s[tid] = g_e2[nt * NTT + tid];
        const char* Bg0 = (const char*)g_B + ((size_t)(nt * NTT + lr) * K3B) * 2 + lc * 16;

        {
            CP_ASYNC16(sA + stA,              Ag0);
            CP_ASYNC16(sA + stA + 64 * PITCH, Ag0 + (size_t)64 * K3A * 2);
            CP_ASYNC16(sB + stA,              Bg0);
            CP_ASYNC16(sB + stA + 64 * PITCH, Bg0 + (size_t)64 * K3B * 2);
            CP_COMMIT();
        }
        float acc[2][8][4];
        #pragma unroll
        for (int i = 0; i < 2; i++)
            #pragma unroll
            for (int j = 0; j < 8; j++)
                #pragma unroll
                for (int x = 0; x < 4; x++) acc[i][j][x] = 0.0f;
        CP_WAIT0();
        __syncthreads();

        #pragma unroll 1
        for (int kt = 0; kt < NKT; kt++) {
            int cur = kt & 1;
            if (kt < NKT - 1) {
                int nxt = 1 - cur;
                size_t goA = (size_t)((kt + 1) & 7) * (KTILE * 2);
                size_t goB = (size_t)(kt + 1) * (KTILE * 2);
                CP_ASYNC16(sA + nxt * ABUFB + stA,              Ag0 + goA);
                CP_ASYNC16(sA + nxt * ABUFB + stA + 64 * PITCH, Ag0 + goA + (size_t)64 * K3A * 2);
                CP_ASYNC16(sB + nxt * ABUFB + stA,              Bg0 + goB);
                CP_ASYNC16(sB + nxt * ABUFB + stA + 64 * PITCH, Bg0 + goB + (size_t)64 * K3B * 2);
                CP_COMMIT();
            }
            uint32_t abase = sA + cur * ABUFB + aoff0;
            uint32_t bbase = sB + cur * ABUFB + boff0;
            #pragma unroll
            for (int ks = 0; ks < 2; ks++) {
                uint32_t af[2][4];
                #pragma unroll
                for (int mf = 0; mf < 2; mf++)
                    ldsm_x4(af[mf][0], af[mf][1], af[mf][2], af[mf][3],
                            abase + mf * (16 * PITCH) + ks * 32);
                #pragma unroll
                for (int nf2 = 0; nf2 < 4; nf2++) {
                    uint32_t r0, r1, r2, r3;
                    ldsm_x4(r0, r1, r2, r3, bbase + nf2 * (16 * PITCH) + ks * 32);
                    #pragma unroll
                    for (int mf = 0; mf < 2; mf++) {
                        mma16816(acc[mf][nf2 * 2],     af[mf][0], af[mf][1], af[mf][2], af[mf][3], r0, r1);
                        mma16816(acc[mf][nf2 * 2 + 1], af[mf][0], af[mf][1], af[mf][2], af[mf][3], r2, r3);
                    }
                }
            }
            if (kt < NKT - 1) CP_WAIT0();
            __syncthreads();
        }

        int c0 = (lane & 3) * 2;
        #pragma unroll
        for (int mf = 0; mf < 2; mf++) {
            #pragma unroll
            for (int nf = 0; nf < 8; nf++) {
                int loc = nhalf * 64 + nf * 8 + c0;
                int k0 = nt * NTT + loc;
                float e20 = e2s[loc], e21 = e2s[loc + 1];
                float s;
                int qa = mf * 2, qb = mf * 2 + 1;
                s = fmaf(-2.0f, acc[mf][nf][0], e20);
                if (s < B1r[qa]) { B2r[qa] = B1r[qa]; B1r[qa] = s; I1r[qa] = k0; } else if (s < B2r[qa]) B2r[qa] = s;
                s = fmaf(-2.0f, acc[mf][nf][1], e21);
                if (s < B1r[qa]) { B2r[qa] = B1r[qa]; B1r[qa] = s; I1r[qa] = k0 + 1; } else if (s < B2r[qa]) B2r[qa] = s;
                s = fmaf(-2.0f, acc[mf][nf][2], e20);
                if (s < B1r[qb]) { B2r[qb] = B1r[qb]; B1r[qb] = s; I1r[qb] = k0; } else if (s < B2r[qb]) B2r[qb] = s;
                s = fmaf(-2.0f, acc[mf][nf][3], e21);
                if (s < B1r[qb]) { B2r[qb] = B1r[qb]; B1r[qb] = s; I1r[qb] = k0 + 1; } else if (s < B2r[qb]) B2r[qb] = s;
            }
        }
        __syncthreads();
    }

    #pragma unroll
    for (int q = 0; q < 4; q++) {
        #pragma unroll
        for (int m = 1; m <= 2; m <<= 1) {
            float ob1 = __shfl_xor_sync(0xffffffffu, B1r[q], m);
            int   oi1 = __shfl_xor_sync(0xffffffffu, I1r[q], m);
            float ob2 = __shfl_xor_sync(0xffffffffu, B2r[q], m);
            if (ob1 < B1r[q] || (ob1 == B1r[q] && oi1 < I1r[q])) {
                B2r[q] = fminf(B1r[q], ob2); B1r[q] = ob1; I1r[q] = oi1;
            } else B2r[q] = fminf(B2r[q], ob1);
        }
    }
    if ((lane & 3) == 0) {
        int r = lane >> 2;
        #pragma unroll
        for (int mf = 0; mf < 2; mf++)
            #pragma unroll
            for (int rh = 0; rh < 2; rh++) {
                int q = mf * 2 + rh;
                int row = m0w + mf * 16 + r + rh * 8;
                sv1[nhalf][row] = B1r[q];
                sv2[nhalf][row] = B2r[q];
                si[nhalf][row]  = I1r[q];
            }
    }
    __syncthreads();
    if (tid < MT) {
        float a1 = sv1[0][tid], a2 = sv2[0][tid]; int ai = si[0][tid];
        float c1 = sv1[1][tid], c2 = sv2[1][tid]; int ci = si[1][tid];
        float best, second; int bi;
        if (a1 < c1 || (a1 == c1 && ai < ci)) { best = a1; bi = ai; second = fminf(a2, c1); }
        else                                  { best = c1; bi = ci; second = fminf(c2, a1); }
        g_idx[m0 + tid] = bi;
        if (second - best < MARGIN) {
            int p = atomicAdd(&g_nflag, 1);
            g_flaglist[p] = m0 + tid;
            g_bestf[p] = 0xFFFFFFFFFFFFFFFFull;
        }
    }
}

// ---------------- K2b (#5): exact fp32 refine (coalesced, atomicMin) ----------------
__global__ void k_refine(const float* __restrict__ emb) {
    __shared__ float zr[DIM];
    __shared__ unsigned long long wbest[8];
    int t = threadIdx.x;
    int w = t >> 5, lane = t & 31;
    int total = g_nflag * 8;
    for (int item = blockIdx.x; item < total; item += gridDim.x) {
        int f = item >> 3, ch = item & 7;
        int n = g_flaglist[f];
        zr[t] = g_flatz[(size_t)n * DIM + t];
        __syncthreads();
        float zf[8];
        #pragma unroll
        for (int i = 0; i < 8; i++) zf[i] = zr[lane * 8 + i];
        unsigned long long best = 0xFFFFFFFFFFFFFFFFull;
        int k0 = ch * 128 + w * 16;
        #pragma unroll 2
        for (int kk = 0; kk < 16; kk++) {
            int k = k0 + kk;
            const float4* er = (const float4*)(emb + (size_t)k * DIM);
            float4 ea = er[lane * 2], eb = er[lane * 2 + 1];
            float p = zf[0] * ea.x;
            p = fmaf(zf[1], ea.y, p);
            p = fmaf(zf[2], ea.z, p);
            p = fmaf(zf[3], ea.w, p);
            p = fmaf(zf[4], eb.x, p);
            p = fmaf(zf[5], eb.y, p);
            p = fmaf(zf[6], eb.z, p);
            p = fmaf(zf[7], eb.w, p);
            #pragma unroll
            for (int m = 16; m > 0; m >>= 1) p += __shfl_xor_sync(0xffffffffu, p, m);
            if (lane == 0) {
                float s = g_e2[k] - 2.0f * p;
                unsigned long long key = ((unsigned long long)fsort(s) << 32) | (unsigned)k;
                if (key < best) best = key;
            }
        }
        if (lane == 0) wbest[w] = best;
        __syncthreads();
        if (t == 0) {
            unsigned long long bb = wbest[0];
            #pragma unroll
            for (int i = 1; i < 8; i++) if (wbest[i] < bb) bb = wbest[i];
            atomicMin(&g_bestf[f], bb);
        }
        __syncthreads();
    }
}

// ---------------- K2c (#6): resolve refined indices ----------------
__global__ void k_resolve() {
    int total = g_nflag;
    for (int i = blockIdx.x * blockDim.x + threadIdx.x; i < total; i += gridDim.x * blockDim.x) {
        int n = g_flaglist[i];
        g_idx[n] = (int)(g_bestf[i] & 0xFFFFFFFFull);
    }
}

// ---------------- K3..K7 ----------------
__global__ void k_counts() {
    int n = blockIdx.x * blockDim.x + threadIdx.x;
    if (n < NPTS) atomicAdd(&g_counts[g_idx[n]], 1.0f);
}
__global__ void k_scatter() {
    int i = blockIdx.x * blockDim.x + threadIdx.x;
    if (i < NPTS * 64) {
        int n = i >> 6, d4 = (i & 63) << 2;
        float4 v = *(const float4*)&g_flatz[(size_t)n * DIM + d4];
        float* dst = &g_dw[g_idx[n] * DIM + d4];
        asm volatile("red.global.add.v4.f32 [%0], {%1,%2,%3,%4};"
                     :: "l"(dst), "f"(v.x), "f"(v.y), "f"(v.z), "f"(v.w) : "memory");
    }
}
__global__ void k_finalize(const float* __restrict__ ema_cs,
                           const float* __restrict__ ema_w,
                           float* __restrict__ out) {
    int k = blockIdx.x, d = threadIdx.x;
    float cs_new = DECAY * ema_cs[k] + ONE_MINUS_DECAY * g_counts[k];
    float w_new  = DECAY * ema_w[k * DIM + d] + ONE_MINUS_DECAY * g_dw[k * DIM + d];
    out[OFF_EMAW + k * DIM + d] = w_new;
    out[OFF_EMB  + k * DIM + d] = w_new / (cs_new + EPS);
    if (d == 0) out[OFF_CS + k] = cs_new;
}
__global__ void k_gather_loss(const float* __restrict__ ze, float* __restrict__ out) {
    int o4 = (blockIdx.x * blockDim.x + threadIdx.x) << 2;
    float sq = 0.0f;
    if (o4 < ZE_ELEMS) {
        int w = o4 & 31, h = (o4 >> 5) & 31, d = (o4 >> 10) & 255, b = o4 >> 18;
        int nb = (b << 10) + (h << 5) + w;
        float4 z = *(const float4*)&ze[o4];
        float q0 = out[OFF_EMB + g_idx[nb]     * DIM + d];
        float q1 = out[OFF_EMB + g_idx[nb + 1] * DIM + d];
        float q2 = out[OFF_EMB + g_idx[nb + 2] * DIM + d];
        float q3 = out[OFF_EMB + g_idx[nb + 3] * DIM + d];
        *(float4*)&out[OFF_ZQ + o4] = make_float4(q0, q1, q2, q3);
        float d0 = z.x - q0, d1 = z.y - q1, d2 = z.z - q2, d3 = z.w - q3;
        sq = d0 * d0 + d1 * d1 + d2 * d2 + d3 * d3;
    }
    #pragma unroll
    for (int off = 16; off > 0; off >>= 1) sq += __shfl_down_sync(0xffffffffu, sq, off);
    __shared__ float ws[8];
    int t = threadIdx.x;
    if ((t & 31) == 0) ws[t >> 5] = sq;
    __syncthreads();
    if (t == 0) {
        float tot = 0.f;
        #pragma unroll
        for (int w2 = 0; w2 < 8; w2++) tot += ws[w2];
        atomicAdd(&g_loss, tot);
    }
}
__global__ void k_tail(float* __restrict__ out) {
    int i = blockIdx.x * blockDim.x + threadIdx.x;
    if (i < NPTS) out[OFF_IDX + i] = (float)g_idx[i];
    if (i == 0)   out[OFF_LOSS] = BETA * g_loss * (1.0f / (float)ZE_ELEMS);
}

// ---------------- launch ----------------
extern "C" void kernel_launch(void* const* d_in, const int* in_sizes, int n_in,
                              void* d_out, int out_size) {
    const float* z_e    = (const float*)d_in[0];
    const float* emb    = (const float*)d_in[1];
    const float* ema_cs = (const float*)d_in[2];
    const float* ema_w  = (const float*)d_in[3];
    float* out = (float*)d_out;

    k_init<<<(KC * DIM + 255) / 256, 256>>>();            // #1
    k_split_z<<<(NPTS / 16) * 2, 256>>>(z_e);             // #2
    k_split_emb<<<KC, 256>>>(emb);                        // #3
    k_argmin_mma<<<NPTS / MT, 256>>>();                   // #4 <- ncu capture slot
    k_refine<<<1024, 256>>>(emb);                         // #5
    k_resolve<<<128, 256>>>();                            // #6
    k_counts<<<(NPTS + 255) / 256, 256>>>();              // #7
    k_scatter<<<(NPTS * 64 + 255) / 256, 256>>>();        // #8
    k_finalize<<<KC, DIM>>>(ema_cs, ema_w, out);          // #9
    k_gather_loss<<<(ZE_ELEMS / 4 + 255) / 256, 256>>>(z_e, out);  // #10
    k_tail<<<(NPTS + 255) / 256, 256>>>(out);             // #11
}

// round 15
// speedup vs baseline: 1.5628x; 1.5628x over previous
#include <cuda_runtime.h>
#include <cuda_bf16.h>
#include <cstdint>
#include <math.h>

// ---------------- problem constants ----------------
#define NB   32
#define HH   32
#define WW   32
#define NPTS 32768
#define DIM  256
#define KC   1024
#define DECAY 0.99f
#define ONE_MINUS_DECAY 0.01f
#define EPS 1e-5f
#define BETA 0.25f
#define ZE_ELEMS (NB*DIM*HH*WW)

// output layout
#define OFF_ZQ    0
#define OFF_LOSS  8388608
#define OFF_IDX   8388609
#define OFF_EMB   8421377
#define OFF_CS    8683521
#define OFF_EMAW  8684545

// ---------------- GEMM config (K'=768 split: [A1|A1|A2].[B1|B2|B1]) ----------------
#define K3    768
#define MT    128
#define NTT   128
#define NTILES 8
#define KTILE 32
#define NKT   24
#define PITCH 80
#define ABUFB (MT * PITCH)        // 10240
#define STAGES 4
#define STGB  (2 * ABUFB)         // A+B per stage = 20480
#define SM_E2   (STAGES * STGB)   // 81920
#define SM_SV1  (SM_E2 + 4096)    // 86016
#define SM_SV2  (SM_SV1 + 1024)
#define SM_SI   (SM_SV1 + 2048)
#define DSMEM   (SM_SV1 + 3072)   // 89088
#define MARGIN 0.08f

// ---------------- device scratch ----------------
__device__ float g_flatz[NPTS * DIM];
__device__ float g_e2[KC];
__device__ int   g_idx[NPTS];
__device__ float g_counts[KC];
__device__ float g_dw[KC * DIM];
__device__ float g_loss;
__device__ __align__(16) __nv_bfloat16 g_A[(size_t)NPTS * K3];
__device__ __align__(16) __nv_bfloat16 g_B[(size_t)KC * K3];
__device__ int g_nflag;
__device__ int g_flaglist[NPTS];
__device__ unsigned long long g_bestf[NPTS];

__device__ __forceinline__ uint32_t smem_u32(const void* p) {
    uint32_t a;
    asm("{ .reg .u64 t; cvta.to.shared.u64 t, %1; cvt.u32.u64 %0, t; }" : "=r"(a) : "l"(p));
    return a;
}
__device__ __forceinline__ void ldsm_x4(uint32_t& r0, uint32_t& r1, uint32_t& r2, uint32_t& r3, uint32_t a) {
    asm volatile("ldmatrix.sync.aligned.m8n8.x4.shared.b16 {%0,%1,%2,%3}, [%4];"
                 : "=r"(r0), "=r"(r1), "=r"(r2), "=r"(r3) : "r"(a));
}
__device__ __forceinline__ void mma16816(float* c, uint32_t a0, uint32_t a1, uint32_t a2, uint32_t a3,
                                         uint32_t b0, uint32_t b1) {
    asm volatile("mma.sync.aligned.m16n8k16.row.col.f32.bf16.bf16.f32 "
                 "{%0,%1,%2,%3}, {%4,%5,%6,%7}, {%8,%9}, {%0,%1,%2,%3};"
                 : "+f"(c[0]), "+f"(c[1]), "+f"(c[2]), "+f"(c[3])
                 : "r"(a0), "r"(a1), "r"(a2), "r"(a3), "r"(b0), "r"(b1));
}
#define CP_ASYNC16(sm, gm) asm volatile("cp.async.cg.shared.global [%0], [%1], 16;" :: "r"(sm), "l"(gm))
#define CP_COMMIT()        asm volatile("cp.async.commit_group;" ::: "memory")
#define CP_WAIT2()         asm volatile("cp.async.wait_group 2;" ::: "memory")

__device__ __forceinline__ unsigned int fsort(float s) {
    unsigned int u = __float_as_uint(s);
    return (u & 0x80000000u) ? ~u : (u | 0x80000000u);
}

// ---------------- K0 (#1) ----------------
__global__ void k_init() {
    int i = blockIdx.x * blockDim.x + threadIdx.x;
    if (i < KC * DIM) g_dw[i] = 0.0f;
    if (i < KC)       g_counts[i] = 0.0f;
    if (i == 0)       { g_loss = 0.0f; g_nflag = 0; }
}

// ---------------- K1 (#2): transpose + bf16 split of z ----------------
__global__ void k_split_z(const float* __restrict__ ze) {
    __shared__ float ts[128][17];
    int b  = blockIdx.x;
    int n0 = (b >> 1) * 16;
    int d0 = (b & 1) * 128;
    int bz = n0 >> 10;
    int hw0 = n0 & 1023;
    int t = threadIdx.x;

    const float* src = ze + (size_t)bz * DIM * (HH * WW) + (size_t)d0 * (HH * WW) + hw0;
    #pragma unroll
    for (int i = 0; i < 2; i++) {
        int chunk = t + i * 256;
        int d = chunk >> 2, c = chunk & 3;
        float4 v = *(const float4*)(src + (size_t)d * (HH * WW) + c * 4);
        ts[d][c * 4 + 0] = v.x;
        ts[d][c * 4 + 1] = v.y;
        ts[d][c * 4 + 2] = v.z;
        ts[d][c * 4 + 3] = v.w;
    }
    __syncthreads();

    int n_l = t >> 4, c16 = t & 15;
    int n = n0 + n_l;
    int dd0 = c16 * 8;
    float v[8];
    #pragma unroll
    for (int j = 0; j < 8; j++) v[j] = ts[dd0 + j][n_l];

    float4* fz = (float4*)&g_flatz[(size_t)n * DIM + d0 + dd0];
    fz[0] = make_float4(v[0], v[1], v[2], v[3]);
    fz[1] = make_float4(v[4], v[5], v[6], v[7]);

    uint4 p1, p2;
    uint32_t* w1 = (uint32_t*)&p1;
    uint32_t* w2 = (uint32_t*)&p2;
    #pragma unroll
    for (int j2 = 0; j2 < 4; j2++) {
        __nv_bfloat16 a1 = __float2bfloat16(v[2 * j2]);
        __nv_bfloat16 b1 = __float2bfloat16(v[2 * j2 + 1]);
        __nv_bfloat16 a2 = __float2bfloat16(v[2 * j2]     - __bfloat162float(a1));
        __nv_bfloat16 b2 = __float2bfloat16(v[2 * j2 + 1] - __bfloat162float(b1));
        __nv_bfloat162 hp(a1, b1), lp(a2, b2);
        w1[j2] = *(uint32_t*)&hp;
        w2[j2] = *(uint32_t*)&lp;
    }
    __nv_bfloat16* arow = &g_A[(size_t)n * K3];
    *(uint4*)(arow + d0 + dd0)       = p1;
    *(uint4*)(arow + 256 + d0 + dd0) = p1;
    *(uint4*)(arow + 512 + d0 + dd0) = p2;
}

// ---------------- K1b (#3): split emb [B1|B2|B1] + ||e||^2 ----------------
__global__ void k_split_emb(const float* __restrict__ emb) {
    int k = blockIdx.x, t = threadIdx.x;
    float v = emb[k * DIM + t];
    __nv_bfloat16 b1 = __float2bfloat16(v);
    __nv_bfloat16 b2 = __float2bfloat16(v - __bfloat162float(b1));
    size_t base = (size_t)k * K3 + t;
    g_B[base]       = b1;
    g_B[base + 256] = b2;
    g_B[base + 512] = b1;
    float s = v * v;
    #pragma unroll
    for (int o = 16; o > 0; o >>= 1) s += __shfl_down_sync(0xffffffffu, s, o);
    __shared__ float ws[8];
    if ((t & 31) == 0) ws[t >> 5] = s;
    __syncthreads();
    if (t == 0) {
        float tot = 0.f;
        #pragma unroll
        for (int w = 0; w < 8; w++) tot += ws[w];
        g_e2[k] = tot;
    }
}

// ---------------- K2 (#4, ncu slot): HMMA GEMM + argmin, 4-stage cp.async ----------------
__global__ __launch_bounds__(256, 2) void k_argmin_mma() {
    extern __shared__ __align__(128) char dyn[];
    uint32_t base = smem_u32(dyn);
    float* e2all = (float*)(dyn + SM_E2);
    float* sv1   = (float*)(dyn + SM_SV1);
    float* sv2   = (float*)(dyn + SM_SV2);
    int*   si    = (int*)(dyn + SM_SI);

    int tid  = threadIdx.x;
    int lane = tid & 31;
    int w    = tid >> 5;
    int mgrp = w & 3, nhalf = w >> 2;
    int m0   = blockIdx.x * MT;
    int m0w  = mgrp * 32;

    int lr = tid >> 2, lc = tid & 3;
    const char* Ag0 = (const char*)g_A + ((size_t)(m0 + lr) * K3) * 2 + lc * 16;
    uint32_t stA = lr * PITCH + lc * 16;

    // e2 once for all tiles
    #pragma unroll
    for (int i = 0; i < KC / 256; i++) e2all[tid + i * 256] = g_e2[tid + i * 256];

    uint32_t aoff0 = (m0w + (lane & 15)) * PITCH + (lane >> 4) * 16;
    uint32_t boff0 = (nhalf * 64 + (lane & 7) + ((lane >> 4) << 3)) * PITCH + ((lane >> 3) & 1) * 16;

    float B1r[4] = {3.4e38f, 3.4e38f, 3.4e38f, 3.4e38f};
    float B2r[4] = {3.4e38f, 3.4e38f, 3.4e38f, 3.4e38f};
    int   I1r[4] = {0, 0, 0, 0};

    for (int nt = 0; nt < NTILES; nt++) {
        const char* Bg0 = (const char*)g_B + ((size_t)(nt * NTT + lr) * K3) * 2 + lc * 16;

        // prologue: stages 0..2
        #pragma unroll
        for (int s = 0; s < 3; s++) {
            size_t go = (size_t)s * (KTILE * 2);
            uint32_t sb = base + s * STGB;
            CP_ASYNC16(sb + stA,                      Ag0 + go);
            CP_ASYNC16(sb + stA + 64 * PITCH,         Ag0 + go + (size_t)64 * K3 * 2);
            CP_ASYNC16(sb + ABUFB + stA,              Bg0 + go);
            CP_ASYNC16(sb + ABUFB + stA + 64 * PITCH, Bg0 + go + (size_t)64 * K3 * 2);
            CP_COMMIT();
        }
        float acc[2][8][4];
        #pragma unroll
        for (int i = 0; i < 2; i++)
            #pragma unroll
            for (int j = 0; j < 8; j++)
                #pragma unroll
                for (int x = 0; x < 4; x++) acc[i][j][x] = 0.0f;

        #pragma unroll 1
        for (int kt = 0; kt < NKT; kt++) {
            CP_WAIT2();                 // tile kt complete (pending <= kt+1, kt+2)
            __syncthreads();            // visible to all; stage (kt+3)&3 free
            if (kt + 3 < NKT) {
                size_t go = (size_t)(kt + 3) * (KTILE * 2);
                uint32_t sb = base + ((kt + 3) & 3) * STGB;
                CP_ASYNC16(sb + stA,                      Ag0 + go);
                CP_ASYNC16(sb + stA + 64 * PITCH,         Ag0 + go + (size_t)64 * K3 * 2);
                CP_ASYNC16(sb + ABUFB + stA,              Bg0 + go);
                CP_ASYNC16(sb + ABUFB + stA + 64 * PITCH, Bg0 + go + (size_t)64 * K3 * 2);
            }
            CP_COMMIT();                // always (keeps group arithmetic fixed)

            uint32_t sb = base + (kt & 3) * STGB;
            uint32_t abase = sb + aoff0;
            uint32_t bbase = sb + ABUFB + boff0;
            #pragma unroll
            for (int ks = 0; ks < 2; ks++) {
                uint32_t af[2][4];
                #pragma unroll
                for (int mf = 0; mf < 2; mf++)
                    ldsm_x4(af[mf][0], af[mf][1], af[mf][2], af[mf][3],
                            abase + mf * (16 * PITCH) + ks * 32);
                #pragma unroll
                for (int nf2 = 0; nf2 < 4; nf2++) {
                    uint32_t r0, r1, r2, r3;
                    ldsm_x4(r0, r1, r2, r3, bbase + nf2 * (16 * PITCH) + ks * 32);
                    #pragma unroll
                    for (int mf = 0; mf < 2; mf++) {
                        mma16816(acc[mf][nf2 * 2],     af[mf][0], af[mf][1], af[mf][2], af[mf][3], r0, r1);
                        mma16816(acc[mf][nf2 * 2 + 1], af[mf][0], af[mf][1], af[mf][2], af[mf][3], r2, r3);
                    }
                }
            }
        }

        // epilogue: scores + running argmin (e2all is read-only; no barrier needed)
        int c0 = (lane & 3) * 2;
        #pragma unroll
        for (int mf = 0; mf < 2; mf++) {
            #pragma unroll
            for (int nf = 0; nf < 8; nf++) {
                int loc = nhalf * 64 + nf * 8 + c0;
                int k0 = nt * NTT + loc;
                float e20 = e2all[k0], e21 = e2all[k0 + 1];
                float s;
                int qa = mf * 2, qb = mf * 2 + 1;
                s = fmaf(-2.0f, acc[mf][nf][0], e20);
                if (s < B1r[qa]) { B2r[qa] = B1r[qa]; B1r[qa] = s; I1r[qa] = k0; } else if (s < B2r[qa]) B2r[qa] = s;
                s = fmaf(-2.0f, acc[mf][nf][1], e21);
                if (s < B1r[qa]) { B2r[qa] = B1r[qa]; B1r[qa] = s; I1r[qa] = k0 + 1; } else if (s < B2r[qa]) B2r[qa] = s;
                s = fmaf(-2.0f, acc[mf][nf][2], e20);
                if (s < B1r[qb]) { B2r[qb] = B1r[qb]; B1r[qb] = s; I1r[qb] = k0; } else if (s < B2r[qb]) B2r[qb] = s;
                s = fmaf(-2.0f, acc[mf][nf][3], e21);
                if (s < B1r[qb]) { B2r[qb] = B1r[qb]; B1r[qb] = s; I1r[qb] = k0 + 1; } else if (s < B2r[qb]) B2r[qb] = s;
            }
        }
    }

    #pragma unroll
    for (int q = 0; q < 4; q++) {
        #pragma unroll
        for (int m = 1; m <= 2; m <<= 1) {
            float ob1 = __shfl_xor_sync(0xffffffffu, B1r[q], m);
            int   oi1 = __shfl_xor_sync(0xffffffffu, I1r[q], m);
            float ob2 = __shfl_xor_sync(0xffffffffu, B2r[q], m);
            if (ob1 < B1r[q] || (ob1 == B1r[q] && oi1 < I1r[q])) {
                B2r[q] = fminf(B1r[q], ob2); B1r[q] = ob1; I1r[q] = oi1;
            } else B2r[q] = fminf(B2r[q], ob1);
        }
    }
    __syncthreads();   // all compute done before sv reuse of smem region
    if ((lane & 3) == 0) {
        int r = lane >> 2;
        #pragma unroll
        for (int mf = 0; mf < 2; mf++)
            #pragma unroll
            for (int rh = 0; rh < 2; rh++) {
                int q = mf * 2 + rh;
                int row = m0w + mf * 16 + r + rh * 8;
                sv1[nhalf * MT + row] = B1r[q];
                sv2[nhalf * MT + row] = B2r[q];
                si[nhalf * MT + row]  = I1r[q];
            }
    }
    __syncthreads();
    if (tid < MT) {
        float a1 = sv1[tid], a2 = sv2[tid]; int ai = si[tid];
        float c1 = sv1[MT + tid], c2 = sv2[MT + tid]; int ci = si[MT + tid];
        float best, second; int bi;
        if (a1 < c1 || (a1 == c1 && ai < ci)) { best = a1; bi = ai; second = fminf(a2, c1); }
        else                                  { best = c1; bi = ci; second = fminf(c2, a1); }
        g_idx[m0 + tid] = bi;
        if (second - best < MARGIN) {
            int p = atomicAdd(&g_nflag, 1);
            g_flaglist[p] = m0 + tid;
            g_bestf[p] = 0xFFFFFFFFFFFFFFFFull;
        }
    }
}

// ---------------- K2b (#5): exact fp32 refine (coalesced, atomicMin) ----------------
__global__ void k_refine(const float* __restrict__ emb) {
    __shared__ float zr[DIM];
    __shared__ unsigned long long wbest[8];
    int t = threadIdx.x;
    int w = t >> 5, lane = t & 31;
    int total = g_nflag * 8;
    for (int item = blockIdx.x; item < total; item += gridDim.x) {
        int f = item >> 3, ch = item & 7;
        int n = g_flaglist[f];
        zr[t] = g_flatz[(size_t)n * DIM + t];
        __syncthreads();
        float zf[8];
        #pragma unroll
        for (int i = 0; i < 8; i++) zf[i] = zr[lane * 8 + i];
        unsigned long long best = 0xFFFFFFFFFFFFFFFFull;
        int k0 = ch * 128 + w * 16;
        #pragma unroll 2
        for (int kk = 0; kk < 16; kk++) {
            int k = k0 + kk;
            const float4* er = (const float4*)(emb + (size_t)k * DIM);
            float4 ea = er[lane * 2], eb = er[lane * 2 + 1];
            float p = zf[0] * ea.x;
            p = fmaf(zf[1], ea.y, p);
            p = fmaf(zf[2], ea.z, p);
            p = fmaf(zf[3], ea.w, p);
            p = fmaf(zf[4], eb.x, p);
            p = fmaf(zf[5], eb.y, p);
            p = fmaf(zf[6], eb.z, p);
            p = fmaf(zf[7], eb.w, p);
            #pragma unroll
            for (int m = 16; m > 0; m >>= 1) p += __shfl_xor_sync(0xffffffffu, p, m);
            if (lane == 0) {
                float s = g_e2[k] - 2.0f * p;
                unsigned long long key = ((unsigned long long)fsort(s) << 32) | (unsigned)k;
                if (key < best) best = key;
            }
        }
        if (lane == 0) wbest[w] = best;
        __syncthreads();
        if (t == 0) {
            unsigned long long bb = wbest[0];
            #pragma unroll
            for (int i = 1; i < 8; i++) if (wbest[i] < bb) bb = wbest[i];
            atomicMin(&g_bestf[f], bb);
        }
        __syncthreads();
    }
}

// ---------------- K2c (#6): resolve ----------------
__global__ void k_resolve() {
    int total = g_nflag;
    for (int i = blockIdx.x * blockDim.x + threadIdx.x; i < total; i += gridDim.x * blockDim.x) {
        int n = g_flaglist[i];
        g_idx[n] = (int)(g_bestf[i] & 0xFFFFFFFFull);
    }
}

// ---------------- K3..K7 ----------------
__global__ void k_counts() {
    int n = blockIdx.x * blockDim.x + threadIdx.x;
    if (n < NPTS) atomicAdd(&g_counts[g_idx[n]], 1.0f);
}
__global__ void k_scatter() {
    int i = blockIdx.x * blockDim.x + threadIdx.x;
    if (i < NPTS * 64) {
        int n = i >> 6, d4 = (i & 63) << 2;
        float4 v = *(const float4*)&g_flatz[(size_t)n * DIM + d4];
        float* dst = &g_dw[g_idx[n] * DIM + d4];
        asm volatile("red.global.add.v4.f32 [%0], {%1,%2,%3,%4};"
                     :: "l"(dst), "f"(v.x), "f"(v.y), "f"(v.z), "f"(v.w) : "memory");
    }
}
__global__ void k_finalize(const float* __restrict__ ema_cs,
                           const float* __restrict__ ema_w,
                           float* __restrict__ out) {
    int k = blockIdx.x, d = threadIdx.x;
    float cs_new = DECAY * ema_cs[k] + ONE_MINUS_DECAY * g_counts[k];
    float w_new  = DECAY * ema_w[k * DIM + d] + ONE_MINUS_DECAY * g_dw[k * DIM + d];
    out[OFF_EMAW + k * DIM + d] = w_new;
    out[OFF_EMB  + k * DIM + d] = w_new / (cs_new + EPS);
    if (d == 0) out[OFF_CS + k] = cs_new;
}
__global__ void k_gather_loss(const float* __restrict__ ze, float* __restrict__ out) {
    int o4 = (blockIdx.x * blockDim.x + threadIdx.x) << 2;
    float sq = 0.0f;
    if (o4 < ZE_ELEMS) {
        int w = o4 & 31, h = (o4 >> 5) & 31, d = (o4 >> 10) & 255, b = o4 >> 18;
        int nb = (b << 10) + (h << 5) + w;
        float4 z = *(const float4*)&ze[o4];
        float q0 = out[OFF_EMB + g_idx[nb]     * DIM + d];
        float q1 = out[OFF_EMB + g_idx[nb + 1] * DIM + d];
        float q2 = out[OFF_EMB + g_idx[nb + 2] * DIM + d];
        float q3 = out[OFF_EMB + g_idx[nb + 3] * DIM + d];
        *(float4*)&out[OFF_ZQ + o4] = make_float4(q0, q1, q2, q3);
        float d0 = z.x - q0, d1 = z.y - q1, d2 = z.z - q2, d3 = z.w - q3;
        sq = d0 * d0 + d1 * d1 + d2 * d2 + d3 * d3;
    }
    #pragma unroll
    for (int off = 16; off > 0; off >>= 1) sq += __shfl_down_sync(0xffffffffu, sq, off);
    __shared__ float ws[8];
    int t = threadIdx.x;
    if ((t & 31) == 0) ws[t >> 5] = sq;
    __syncthreads();
    if (t == 0) {
        float tot = 0.f;
        #pragma unroll
        for (int w2 = 0; w2 < 8; w2++) tot += ws[w2];
        atomicAdd(&g_loss, tot);
    }
}
__global__ void k_tail(float* __restrict__ out) {
    int i = blockIdx.x * blockDim.x + threadIdx.x;
    if (i < NPTS) out[OFF_IDX + i] = (float)g_idx[i];
    if (i == 0)   out[OFF_LOSS] = BETA * g_loss * (1.0f / (float)ZE_ELEMS);
}

// ---------------- launch ----------------
extern "C" void kernel_launch(void* const* d_in, const int* in_sizes, int n_in,
                              void* d_out, int out_size) {
    const float* z_e    = (const float*)d_in[0];
    const float* emb    = (const float*)d_in[1];
    const float* ema_cs = (const float*)d_in[2];
    const float* ema_w  = (const float*)d_in[3];
    float* out = (float*)d_out;

    cudaFuncSetAttribute(k_argmin_mma, cudaFuncAttributeMaxDynamicSharedMemorySize, DSMEM);

    k_init<<<(KC * DIM + 255) / 256, 256>>>();            // #1
    k_split_z<<<(NPTS / 16) * 2, 256>>>(z_e);             // #2
    k_split_emb<<<KC, 256>>>(emb);                        // #3
    k_argmin_mma<<<NPTS / MT, 256, DSMEM>>>();            // #4 <- ncu capture slot
    k_refine<<<1024, 256>>>(emb);                         // #5
    k_resolve<<<128, 256>>>();                            // #6
    k_counts<<<(NPTS + 255) / 256, 256>>>();              // #7
    k_scatter<<<(NPTS * 64 + 255) / 256, 256>>>();        // #8
    k_finalize<<<KC, DIM>>>(ema_cs, ema_w, out);          // #9
    k_gather_loss<<<(ZE_ELEMS / 4 + 255) / 256, 256>>>(z_e, out);  // #10
    k_tail<<<(NPTS + 255) / 256, 256>>>(out);             // #11
}